// round 5
// baseline (speedup 1.0000x reference)
#include <cuda_runtime.h>
#include <cuda_bf16.h>
#include <cstdint>

// ---------------- problem constants ----------------
#define Bc     2
#define Nc     768
#define Dc     2048
#define CLIPc  1024
#define Jc     7
#define Lc     25
#define HPc    24
#define HWc    576
#define PATCHc 14
#define IMGc   336
#define PKc    588
#define SLc    601
#define SCALEc 0.03125f
#define LN_EPSc 1e-5f
#define COS_EPSc 1e-8f
#define IMG_TOK (-200)
#define MPAD   640
#define KCLIP  640

// ---------------- device scratch ----------------
__device__ int            g_idx[Bc];
__device__ __nv_bfloat16  g_patb [(size_t)Bc * MPAD * KCLIP];
__device__ __nv_bfloat16  g_xnb  [(size_t)Bc * Jc * MPAD * Dc];
__device__ __nv_bfloat16  g_f24b [(size_t)Bc * MPAD * Dc];
__device__ __nv_bfloat16  g_fuseb[(size_t)Bc * MPAD * CLIPc];
__device__ __nv_bfloat16  w_norm [(size_t)Jc * CLIPc * Dc];
__device__ __nv_bfloat16  w_input[(size_t)CLIPc * Dc];
__device__ __nv_bfloat16  w_output[(size_t)CLIPc * CLIPc];
__device__ __nv_bfloat16  w_clip [(size_t)CLIPc * KCLIP];
__device__ __nv_bfloat16  g_visb [(size_t)Bc * Jc * MPAD * CLIPc];   // bf16 vis
__device__ float g_inp  [(size_t)Bc * MPAD * CLIPc];
__device__ float g_outm [(size_t)Bc * MPAD * CLIPc];
__device__ float g_clipf[(size_t)Bc * MPAD * CLIPc];
__device__ float g_cos  [Bc * HWc];

// ---------------- helpers ----------------
__device__ __forceinline__ uint32_t smem_u32(const void* p) {
    uint32_t a;
    asm("{ .reg .u64 t; cvta.to.shared.u64 t, %1; cvt.u32.u64 %0, t; }" : "=r"(a) : "l"(p));
    return a;
}
__device__ __forceinline__ void cp16(uint32_t s, const void* g) {
    asm volatile("cp.async.cg.shared.global [%0], [%1], 16;" :: "r"(s), "l"(g));
}
#define CP_COMMIT() asm volatile("cp.async.commit_group;" ::: "memory")
__device__ __forceinline__ void ldm4(uint32_t* r, uint32_t addr) {
    asm volatile("ldmatrix.sync.aligned.m8n8.x4.shared.b16 {%0,%1,%2,%3}, [%4];"
                 : "=r"(r[0]), "=r"(r[1]), "=r"(r[2]), "=r"(r[3]) : "r"(addr));
}
__device__ __forceinline__ void mma16816(float* d, const uint32_t* a, uint32_t b0, uint32_t b1) {
    asm volatile("mma.sync.aligned.m16n8k16.row.col.f32.bf16.bf16.f32 "
                 "{%0,%1,%2,%3}, {%4,%5,%6,%7}, {%8,%9}, {%0,%1,%2,%3};"
                 : "+f"(d[0]), "+f"(d[1]), "+f"(d[2]), "+f"(d[3])
                 : "r"(a[0]), "r"(a[1]), "r"(a[2]), "r"(a[3]), "r"(b0), "r"(b1));
}
__device__ __forceinline__ uint32_t pkbf(float x, float y) {
    __nv_bfloat162 h = __floats2bfloat162_rn(x, y);
    return *reinterpret_cast<uint32_t*>(&h);
}

// ---------------- kernel: find image-token index ----------------
__global__ void k_find_idx(const int* __restrict__ ids) {
    __shared__ int mn;
    for (int b = 0; b < Bc; ++b) {
        if (threadIdx.x == 0) mn = Nc;
        __syncthreads();
        for (int i = threadIdx.x; i < Nc; i += blockDim.x)
            if (ids[b * Nc + i] == IMG_TOK) atomicMin(&mn, i);
        __syncthreads();
        if (threadIdx.x == 0) {
            int v = mn;
            if (v > Nc - SLc) v = Nc - SLc;
            g_idx[b] = v;
        }
        __syncthreads();
    }
}

// ---------------- kernel: patches -> bf16 padded [B][640][640] ----------------
__global__ void k_patches(const float* __restrict__ images) {
    int p = blockIdx.x, b = blockIdx.y;
    __nv_bfloat16* dst = g_patb + ((size_t)b * MPAD + p) * KCLIP;
    if (p >= HWc) {
        for (int k = threadIdx.x; k < KCLIP; k += 128) dst[k] = __float2bfloat16(0.f);
        return;
    }
    int pr = p / HPc, pc = p % HPc;
    for (int k = threadIdx.x; k < KCLIP; k += 128) {
        float v = 0.f;
        if (k < PKc) {
            int ch = k / 196, rem = k % 196;
            int dy = rem / PATCHc, dx = rem % PATCHc;
            v = images[(((size_t)b * 4 + ch) * IMGc + (pr * PATCHc + dy)) * IMGc
                       + (pc * PATCHc + dx)];
        }
        dst[k] = __float2bfloat16(v);
    }
}

// ---------------- kernel: gather + LayerNorm -> bf16 ----------------
__global__ void k_prep(const float* __restrict__ feats,
                       const float* __restrict__ gamma,
                       const float* __restrict__ beta) {
    int r = blockIdx.x, jj = blockIdx.y, b = blockIdx.z;
    int tid = threadIdx.x;
    __nv_bfloat16* dst = (jj == Jc)
        ? (g_f24b + ((size_t)b * MPAD + r) * Dc)
        : (g_xnb + (((size_t)b * Jc + jj) * MPAD + r) * Dc);
    if (r >= HWc) {
        uint4 z = make_uint4(0, 0, 0, 0);
        ((uint4*)dst)[tid] = z;
        return;
    }
    int t = g_idx[b] + 1 + (r / HPc) * (HPc + 1) + (r % HPc);
    int l = (jj < Jc) ? (24 - 4 * jj) : 24;
    const float* src = feats + (((size_t)b * Nc + t) * Lc + l) * (size_t)Dc;
    float4 a = ((const float4*)src)[tid * 2];
    float4 c = ((const float4*)src)[tid * 2 + 1];
    if (jj == Jc) {
        uint4 u;
        u.x = pkbf(a.x, a.y); u.y = pkbf(a.z, a.w);
        u.z = pkbf(c.x, c.y); u.w = pkbf(c.z, c.w);
        ((uint4*)dst)[tid] = u;
        return;
    }
    float s  = a.x + a.y + a.z + a.w + c.x + c.y + c.z + c.w;
    float s2 = a.x*a.x + a.y*a.y + a.z*a.z + a.w*a.w + c.x*c.x + c.y*c.y + c.z*c.z + c.w*c.w;
    __shared__ float r1[256], r2[256];
    r1[tid] = s; r2[tid] = s2;
    __syncthreads();
    for (int off = 128; off; off >>= 1) {
        if (tid < off) { r1[tid] += r1[tid + off]; r2[tid] += r2[tid + off]; }
        __syncthreads();
    }
    float mu   = r1[0] * (1.f / Dc);
    float var  = r2[0] * (1.f / Dc) - mu * mu;
    float rstd = rsqrtf(var + LN_EPSc);
    const float4* gg = (const float4*)(gamma + (size_t)jj * Dc);
    const float4* bb = (const float4*)(beta  + (size_t)jj * Dc);
    float4 g0 = gg[tid*2], g1 = gg[tid*2+1];
    float4 b0 = bb[tid*2], b1 = bb[tid*2+1];
    float o0 = (a.x - mu) * rstd * g0.x + b0.x;
    float o1 = (a.y - mu) * rstd * g0.y + b0.y;
    float o2 = (a.z - mu) * rstd * g0.z + b0.z;
    float o3 = (a.w - mu) * rstd * g0.w + b0.w;
    float o4 = (c.x - mu) * rstd * g1.x + b1.x;
    float o5 = (c.y - mu) * rstd * g1.y + b1.y;
    float o6 = (c.z - mu) * rstd * g1.z + b1.z;
    float o7 = (c.w - mu) * rstd * g1.w + b1.w;
    uint4 u;
    u.x = pkbf(o0, o1); u.y = pkbf(o2, o3); u.z = pkbf(o4, o5); u.w = pkbf(o6, o7);
    ((uint4*)dst)[tid] = u;
}

// ---------------- merged fp32->bf16 weight conversion ----------------
// blockIdx.y selects tensor: 0=norm_w, 1=input_w, 2=output_w, 3=clip_w (padded)
__global__ void k_cvt_all(const float* __restrict__ nw, const float* __restrict__ iw,
                          const float* __restrict__ ow, const float* __restrict__ cw) {
    int which = blockIdx.y;
    if (which == 3) {
        // clip_w [1024][588] -> [1024][640] bf16 padded
        for (int r = blockIdx.x; r < CLIPc; r += gridDim.x) {
            __nv_bfloat16* d = w_clip + (size_t)r * KCLIP;
            for (int c = threadIdx.x; c < KCLIP; c += blockDim.x)
                d[c] = (c < PKc) ? __float2bfloat16(cw[(size_t)r * PKc + c])
                                 : __float2bfloat16(0.f);
        }
        return;
    }
    const float* s = (which == 0) ? nw : (which == 1) ? iw : ow;
    __nv_bfloat16* d = (which == 0) ? w_norm : (which == 1) ? w_input : w_output;
    int n8 = (which == 0) ? (int)((size_t)Jc * CLIPc * Dc / 8)
           : (which == 1) ? (int)((size_t)CLIPc * Dc / 8)
                          : (int)((size_t)CLIPc * CLIPc / 8);
    for (int i = blockIdx.x * blockDim.x + threadIdx.x; i < n8; i += gridDim.x * blockDim.x) {
        float4 a = ((const float4*)s)[i * 2];
        float4 c = ((const float4*)s)[i * 2 + 1];
        uint4 u;
        u.x = pkbf(a.x, a.y); u.y = pkbf(a.z, a.w);
        u.z = pkbf(c.x, c.y); u.w = pkbf(c.z, c.w);
        ((uint4*)d)[i] = u;
    }
}

// =====================================================================
// GEMM A: big-tile kernel for vis: CTA 128x256, 512 thr, 2-stage cp.async
// C(bf16) = A(bf16,MxK) * B(bf16,NxK)^T        (no bias / no residual)
// =====================================================================
#define STG2_A 8192          // 128 rows x 64B
#define STG2_B 16384         // 256 rows x 64B
#define STG2_SZ 24576

__global__ void __launch_bounds__(512, 1)
k_vgemm(const __nv_bfloat16* __restrict__ A, const __nv_bfloat16* __restrict__ Bw,
        __nv_bfloat16* __restrict__ C, int K,
        long long aStr, long long bStr, int bMod, long long cStr) {
    __shared__ __align__(128) unsigned char smem[2 * STG2_SZ];   // 48 KB
    const int tid = threadIdx.x;
    const int lane = tid & 31, wid = tid >> 5;     // 16 warps
    const int wm = wid & 3, wn = wid >> 2;         // 4x4: warp tile 32(M) x 64(N)
    const int z = blockIdx.z;
    const int m0 = blockIdx.x * 128, n0 = blockIdx.y * 256;
    const __nv_bfloat16* Ab = A + (long long)z * aStr + (long long)m0 * K;
    const __nv_bfloat16* Bb = Bw + (long long)(z % bMod) * bStr + (long long)n0 * K;
    const uint32_t sb = smem_u32(smem);

    float acc[2][8][4];
    #pragma unroll
    for (int i = 0; i < 2; ++i)
        #pragma unroll
        for (int j = 0; j < 8; ++j)
            #pragma unroll
            for (int h = 0; h < 4; ++h) acc[i][j][h] = 0.f;

    // per-thread: 3 x 16B per chunk (A: 512 segs, B: 1024 segs)
    auto load_chunk = [&](int kc, int st) {
        uint32_t base = sb + st * STG2_SZ;
        #pragma unroll
        for (int it = 0; it < 3; ++it) {
            int idx = tid + it * 512;               // 0..1535
            int isB = idx >= 512;
            int o = isB ? (idx - 512) : idx;
            int row = o >> 2, s = o & 3;
            int ps = s ^ ((row >> 1) & 3);
            const __nv_bfloat16* g = (isB ? Bb : Ab) + (size_t)row * K + kc * 32 + s * 8;
            cp16(base + (isB ? STG2_A : 0) + (uint32_t)(row * 64 + ps * 16), g);
        }
    };

    load_chunk(0, 0); CP_COMMIT();

    const int NK = K >> 5;
    for (int k = 0; k < NK; ++k) {
        if (k + 1 < NK) load_chunk(k + 1, (k + 1) & 1);
        CP_COMMIT();
        asm volatile("cp.async.wait_group 1;" ::: "memory");
        __syncthreads();

        uint32_t aBase = sb + (k & 1) * STG2_SZ;
        uint32_t bBase = aBase + STG2_A;
        #pragma unroll
        for (int kk = 0; kk < 2; ++kk) {
            uint32_t afr[2][4];
            #pragma unroll
            for (int im = 0; im < 2; ++im) {
                int row = wm * 32 + im * 16 + (lane & 15);
                int s = kk * 2 + (lane >> 4);
                int ps = s ^ ((row >> 1) & 3);
                ldm4(afr[im], aBase + (uint32_t)(row * 64 + ps * 16));
            }
            uint32_t bfr[4][4];
            #pragma unroll
            for (int ip = 0; ip < 4; ++ip) {
                int row = wn * 64 + ip * 16 + (lane & 15);
                int s = kk * 2 + (lane >> 4);
                int ps = s ^ ((row >> 1) & 3);
                ldm4(bfr[ip], bBase + (uint32_t)(row * 64 + ps * 16));
            }
            #pragma unroll
            for (int im = 0; im < 2; ++im)
                #pragma unroll
                for (int in = 0; in < 8; ++in)
                    mma16816(acc[im][in], afr[im],
                             bfr[in >> 1][in & 1], bfr[in >> 1][(in & 1) + 2]);
        }
        __syncthreads();
    }

    // epilogue: bf16 pairs direct to gmem
    __nv_bfloat16* Cb = C + (long long)z * cStr;
    int g = lane >> 2, q = lane & 3;
    #pragma unroll
    for (int im = 0; im < 2; ++im) {
        #pragma unroll
        for (int in = 0; in < 8; ++in) {
            int col = n0 + wn * 64 + in * 8 + q * 2;
            #pragma unroll
            for (int h = 0; h < 2; ++h) {
                int row = m0 + wm * 32 + im * 16 + g + h * 8;
                uint32_t pv = pkbf(acc[im][in][h * 2], acc[im][in][h * 2 + 1]);
                *(uint32_t*)(Cb + (size_t)row * CLIPc + col) = pv;
            }
        }
    }
}

// =====================================================================
// GEMM B: 128x128 fp32-out kernel for small GEMMs (clip/inp/out)
// =====================================================================
#define BK 32
#define STAGE_A 8192
#define STAGE_SZ 16384

__global__ void __launch_bounds__(256, 2)
k_mgemm(const __nv_bfloat16* __restrict__ A, const __nv_bfloat16* __restrict__ Bw,
        const float* __restrict__ Cadd, const float* __restrict__ bias,
        float* __restrict__ C, int K,
        long long aStr, long long bStr, int bMod, long long cStr) {
    __shared__ __align__(128) unsigned char smem[3 * STAGE_SZ];   // 48 KB
    const int tid = threadIdx.x;
    const int lane = tid & 31, wid = tid >> 5;
    const int wm = wid & 1, wn = wid >> 1;
    const int z = blockIdx.z;
    const int m0 = blockIdx.x * 128, n0 = blockIdx.y * 128;
    const __nv_bfloat16* Ab = A + (long long)z * aStr + (long long)m0 * K;
    const __nv_bfloat16* Bb = Bw + (long long)(z % bMod) * bStr + (long long)n0 * K;
    const uint32_t sb = smem_u32(smem);

    float acc[4][4][4];
    #pragma unroll
    for (int i = 0; i < 4; ++i)
        #pragma unroll
        for (int j = 0; j < 4; ++j)
            #pragma unroll
            for (int h = 0; h < 4; ++h) acc[i][j][h] = 0.f;

    auto load_chunk = [&](int kc, int st) {
        uint32_t base = sb + st * STAGE_SZ;
        #pragma unroll
        for (int it = 0; it < 4; ++it) {
            int idx = tid + it * 256;
            int half = idx >> 9;
            int o = idx & 511;
            int row = o >> 2, s = o & 3;
            int ps = s ^ ((row >> 1) & 3);
            const __nv_bfloat16* g = (half ? Bb : Ab) + (size_t)row * K + kc * BK + s * 8;
            cp16(base + half * STAGE_A + (uint32_t)(row * 64 + ps * 16), g);
        }
    };

    load_chunk(0, 0); CP_COMMIT();
    load_chunk(1, 1); CP_COMMIT();

    const int NK = K >> 5;
    for (int k = 0; k < NK; ++k) {
        asm volatile("cp.async.wait_group 1;" ::: "memory");
        __syncthreads();
        if (k + 2 < NK) load_chunk(k + 2, (k + 2) % 3);
        CP_COMMIT();

        uint32_t aBase = sb + (k % 3) * STAGE_SZ;
        uint32_t bBase = aBase + STAGE_A;
        #pragma unroll
        for (int kk = 0; kk < 2; ++kk) {
            uint32_t afr[4][4];
            #pragma unroll
            for (int im = 0; im < 4; ++im) {
                int row = wm * 64 + im * 16 + (lane & 15);
                int s = kk * 2 + (lane >> 4);
                int ps = s ^ ((row >> 1) & 3);
                ldm4(afr[im], aBase + (uint32_t)(row * 64 + ps * 16));
            }
            uint32_t bfr[2][4];
            #pragma unroll
            for (int ip = 0; ip < 2; ++ip) {
                int row = wn * 32 + ip * 16 + (lane & 15);
                int s = kk * 2 + (lane >> 4);
                int ps = s ^ ((row >> 1) & 3);
                ldm4(bfr[ip], bBase + (uint32_t)(row * 64 + ps * 16));
            }
            #pragma unroll
            for (int im = 0; im < 4; ++im)
                #pragma unroll
                for (int in = 0; in < 4; ++in)
                    mma16816(acc[im][in], afr[im],
                             bfr[in >> 1][in & 1], bfr[in >> 1][(in & 1) + 2]);
        }
        __syncthreads();
    }

    float* Cb = C + (long long)z * cStr;
    const float* CaB = Cadd ? (Cadd + (long long)z * cStr) : nullptr;
    int g = lane >> 2, q = lane & 3;
    #pragma unroll
    for (int im = 0; im < 4; ++im) {
        #pragma unroll
        for (int in = 0; in < 4; ++in) {
            int col = n0 + wn * 32 + in * 8 + q * 2;
            #pragma unroll
            for (int h = 0; h < 2; ++h) {
                int row = m0 + wm * 64 + im * 16 + g + h * 8;
                float2 v = make_float2(acc[im][in][h * 2], acc[im][in][h * 2 + 1]);
                if (bias) { v.x += bias[col]; v.y += bias[col + 1]; }
                if (CaB) {
                    float2 ca = *(const float2*)(CaB + (size_t)row * CLIPc + col);
                    v.x += ca.x; v.y += ca.y;
                }
                *(float2*)(Cb + (size_t)row * CLIPc + col) = v;
            }
        }
    }
}

// ---------------- attention: grid(640, B), 256t = 8 warps = 8 heads, bf16 vis ----------------
__global__ void k_attn() {
    int r = blockIdx.x, b = blockIdx.y;
    int wid = threadIdx.x >> 5, lane = threadIdx.x & 31;
    const __nv_bfloat16* visb = g_visb + (size_t)b * Jc * MPAD * CLIPc;
    size_t rowoff = (size_t)r * CLIPc + wid * 128 + lane;

    float q[4], kv[6][4];
    #pragma unroll
    for (int t = 0; t < 4; ++t) q[t] = __bfloat162float(visb[rowoff + t * 32]) * SCALEc;
    #pragma unroll
    for (int j = 0; j < 6; ++j)
        #pragma unroll
        for (int t = 0; t < 4; ++t)
            kv[j][t] = __bfloat162float(visb[(size_t)(j + 1) * MPAD * CLIPc + rowoff + t * 32]);

    float lg[6];
    #pragma unroll
    for (int j = 0; j < 6; ++j) {
        float s = 0.f;
        #pragma unroll
        for (int t = 0; t < 4; ++t) s += q[t] * kv[j][t];
        #pragma unroll
        for (int off = 16; off; off >>= 1) s += __shfl_xor_sync(0xFFFFFFFFu, s, off);
        lg[j] = s;
    }
    float m = lg[0];
    #pragma unroll
    for (int j = 1; j < 6; ++j) m = fmaxf(m, lg[j]);
    float w[6], sum = 0.f;
    #pragma unroll
    for (int j = 0; j < 6; ++j) { w[j] = __expf(lg[j] - m); sum += w[j]; }
    float inv = 1.f / sum;
    #pragma unroll
    for (int j = 0; j < 6; ++j) w[j] *= inv;

    __nv_bfloat16* dst = g_fuseb + ((size_t)b * MPAD + r) * CLIPc + wid * 128 + lane;
    #pragma unroll
    for (int t = 0; t < 4; ++t) {
        float f = 0.f;
        #pragma unroll
        for (int j = 0; j < 6; ++j) f += w[j] * kv[j][t];
        dst[t * 32] = __float2bfloat16(f);
    }
}

// ---------------- cosine per row ----------------
__global__ void k_cos() {
    int r = blockIdx.x, b = blockIdx.y;
    int tid = threadIdx.x;
    const float* o = g_outm  + ((size_t)b * MPAD + r) * CLIPc;
    const float* c = g_clipf + ((size_t)b * MPAD + r) * CLIPc;
    float d = 0.f, n1 = 0.f, n2 = 0.f;
    #pragma unroll
    for (int i = 0; i < 4; ++i) {
        int k = tid + i * 256;
        float ov = o[k], cv = c[k];
        d += ov * cv; n1 += ov * ov; n2 += cv * cv;
    }
    __shared__ float rd[256], ra[256], rb[256];
    rd[tid] = d; ra[tid] = n1; rb[tid] = n2;
    __syncthreads();
    for (int off = 128; off; off >>= 1) {
        if (tid < off) { rd[tid] += rd[tid + off]; ra[tid] += ra[tid + off]; rb[tid] += rb[tid + off]; }
        __syncthreads();
    }
    if (tid == 0) {
        float denom = fmaxf(sqrtf(ra[0]) * sqrtf(rb[0]), COS_EPSc);
        g_cos[b * HWc + r] = rd[0] / denom;
    }
}

// ---------------- final deterministic reduction ----------------
__global__ void k_final(float* __restrict__ out) {
    int tid = threadIdx.x;
    float s = 0.f;
    for (int i = tid; i < Bc * HWc; i += 256) s += g_cos[i];
    __shared__ float red[256];
    red[tid] = s;
    __syncthreads();
    for (int off = 128; off; off >>= 1) {
        if (tid < off) red[tid] += red[tid + off];
        __syncthreads();
    }
    if (tid == 0) out[0] = 1.f - red[0] * (1.f / (Bc * HWc));
}

// ---------------- host launch ----------------
extern "C" void kernel_launch(void* const* d_in, const int* in_sizes, int n_in,
                              void* d_out, int out_size) {
    const int*   input_ids  = (const int*)  d_in[0];
    const float* images     = (const float*)d_in[1];
    const float* feats      = (const float*)d_in[2];
    const float* norm_gamma = (const float*)d_in[4];
    const float* norm_beta  = (const float*)d_in[5];
    const float* norm_w     = (const float*)d_in[6];
    const float* input_w    = (const float*)d_in[7];
    const float* input_b    = (const float*)d_in[8];
    const float* output_w   = (const float*)d_in[9];
    const float* output_b   = (const float*)d_in[10];
    const float* clip_w     = (const float*)d_in[11];
    const float* clip_b     = (const float*)d_in[12];

    void* p;
    __nv_bfloat16 *p_patb, *p_xnb, *p_f24b, *p_fuseb, *p_wnorm, *p_winp, *p_wout, *p_wclip, *p_visb;
    float *p_inp, *p_outm, *p_clipf;
    cudaGetSymbolAddress(&p, g_patb);   p_patb  = (__nv_bfloat16*)p;
    cudaGetSymbolAddress(&p, g_xnb);    p_xnb   = (__nv_bfloat16*)p;
    cudaGetSymbolAddress(&p, g_f24b);   p_f24b  = (__nv_bfloat16*)p;
    cudaGetSymbolAddress(&p, g_fuseb);  p_fuseb = (__nv_bfloat16*)p;
    cudaGetSymbolAddress(&p, w_norm);   p_wnorm = (__nv_bfloat16*)p;
    cudaGetSymbolAddress(&p, w_input);  p_winp  = (__nv_bfloat16*)p;
    cudaGetSymbolAddress(&p, w_output); p_wout  = (__nv_bfloat16*)p;
    cudaGetSymbolAddress(&p, w_clip);   p_wclip = (__nv_bfloat16*)p;
    cudaGetSymbolAddress(&p, g_visb);   p_visb  = (__nv_bfloat16*)p;
    cudaGetSymbolAddress(&p, g_inp);    p_inp   = (float*)p;
    cudaGetSymbolAddress(&p, g_outm);   p_outm  = (float*)p;
    cudaGetSymbolAddress(&p, g_clipf);  p_clipf = (float*)p;

    k_find_idx<<<1, 256>>>(input_ids);
    k_patches<<<dim3(MPAD, Bc), 128>>>(images);
    k_prep<<<dim3(MPAD, 8, Bc), 256>>>(feats, norm_gamma, norm_beta);
    k_cvt_all<<<dim3(1024, 4), 256>>>(norm_w, input_w, output_w, clip_w);

    // clip_feats = patches @ clip_w^T + clip_b
    k_mgemm<<<dim3(MPAD / 128, CLIPc / 128, Bc), 256>>>(
        p_patb, p_wclip, nullptr, clip_b, p_clipf, KCLIP,
        (long long)MPAD * KCLIP, 0LL, 1, (long long)MPAD * CLIPc);

    // vis[b][j] = xn[b][j] @ norm_w[j]^T  -> bf16 out (big-tile kernel)
    k_vgemm<<<dim3(MPAD / 128, CLIPc / 256, Bc * Jc), 512>>>(
        p_xnb, p_wnorm, p_visb, Dc,
        (long long)MPAD * Dc, (long long)CLIPc * Dc, Jc, (long long)MPAD * CLIPc);

    // inp = f24 @ input_w^T + input_b
    k_mgemm<<<dim3(MPAD / 128, CLIPc / 128, Bc), 256>>>(
        p_f24b, p_winp, nullptr, input_b, p_inp, Dc,
        (long long)MPAD * Dc, 0LL, 1, (long long)MPAD * CLIPc);

    k_attn<<<dim3(MPAD, Bc), 256>>>();

    // out = inp + fuse @ output_w^T + output_b
    k_mgemm<<<dim3(MPAD / 128, CLIPc / 128, Bc), 256>>>(
        p_fuseb, p_wout, p_inp, output_b, p_outm, CLIPc,
        (long long)MPAD * CLIPc, 0LL, 1, (long long)MPAD * CLIPc);

    k_cos<<<dim3(HWc, Bc), 256>>>();
    k_final<<<1, 256>>>((float*)d_out);
}

// round 6
// speedup vs baseline: 1.0245x; 1.0245x over previous
#include <cuda_runtime.h>
#include <cuda_bf16.h>
#include <cstdint>

// ---------------- problem constants ----------------
#define Bc     2
#define Nc     768
#define Dc     2048
#define CLIPc  1024
#define Jc     7
#define Lc     25
#define HPc    24
#define HWc    576
#define PATCHc 14
#define IMGc   336
#define PKc    588
#define SLc    601
#define SCALEc 0.03125f
#define LN_EPSc 1e-5f
#define COS_EPSc 1e-8f
#define IMG_TOK (-200)
#define MPAD   640
#define KCLIP  640

// ---------------- device scratch ----------------
__device__ int            g_idx[Bc];
__device__ __nv_bfloat16  g_patb [(size_t)Bc * MPAD * KCLIP];
__device__ __nv_bfloat16  g_xnb  [(size_t)Bc * Jc * MPAD * Dc];
__device__ __nv_bfloat16  g_f24b [(size_t)Bc * MPAD * Dc];
__device__ __nv_bfloat16  g_fuseb[(size_t)Bc * MPAD * CLIPc];
__device__ __nv_bfloat16  w_norm [(size_t)Jc * CLIPc * Dc];
__device__ __nv_bfloat16  w_input[(size_t)CLIPc * Dc];
__device__ __nv_bfloat16  w_output[(size_t)CLIPc * CLIPc];
__device__ __nv_bfloat16  w_clip [(size_t)CLIPc * KCLIP];
__device__ __nv_bfloat16  g_visb [(size_t)Bc * Jc * MPAD * CLIPc];
__device__ float g_inp  [(size_t)Bc * MPAD * CLIPc];
__device__ float g_outm [(size_t)Bc * MPAD * CLIPc];
__device__ float g_clipf[(size_t)Bc * MPAD * CLIPc];
__device__ float g_cos  [Bc * HWc];

// ---------------- helpers ----------------
__device__ __forceinline__ uint32_t smem_u32(const void* p) {
    uint32_t a;
    asm("{ .reg .u64 t; cvta.to.shared.u64 t, %1; cvt.u32.u64 %0, t; }" : "=r"(a) : "l"(p));
    return a;
}
__device__ __forceinline__ void cp16(uint32_t s, const void* g) {
    asm volatile("cp.async.cg.shared.global [%0], [%1], 16;" :: "r"(s), "l"(g));
}
#define CP_COMMIT() asm volatile("cp.async.commit_group;" ::: "memory")
__device__ __forceinline__ void ldm4(uint32_t* r, uint32_t addr) {
    asm volatile("ldmatrix.sync.aligned.m8n8.x4.shared.b16 {%0,%1,%2,%3}, [%4];"
                 : "=r"(r[0]), "=r"(r[1]), "=r"(r[2]), "=r"(r[3]) : "r"(addr));
}
__device__ __forceinline__ void mma16816(float* d, const uint32_t* a, uint32_t b0, uint32_t b1) {
    asm volatile("mma.sync.aligned.m16n8k16.row.col.f32.bf16.bf16.f32 "
                 "{%0,%1,%2,%3}, {%4,%5,%6,%7}, {%8,%9}, {%0,%1,%2,%3};"
                 : "+f"(d[0]), "+f"(d[1]), "+f"(d[2]), "+f"(d[3])
                 : "r"(a[0]), "r"(a[1]), "r"(a[2]), "r"(a[3]), "r"(b0), "r"(b1));
}
__device__ __forceinline__ uint32_t pkbf(float x, float y) {
    __nv_bfloat162 h = __floats2bfloat162_rn(x, y);
    return *reinterpret_cast<uint32_t*>(&h);
}

// ---------------- kernel: find image-token index ----------------
__global__ void k_find_idx(const int* __restrict__ ids) {
    __shared__ int mn;
    for (int b = 0; b < Bc; ++b) {
        if (threadIdx.x == 0) mn = Nc;
        __syncthreads();
        for (int i = threadIdx.x; i < Nc; i += blockDim.x)
            if (ids[b * Nc + i] == IMG_TOK) atomicMin(&mn, i);
        __syncthreads();
        if (threadIdx.x == 0) {
            int v = mn;
            if (v > Nc - SLc) v = Nc - SLc;
            g_idx[b] = v;
        }
        __syncthreads();
    }
}

// ---------------- kernel: patches -> bf16 padded [B][640][640] ----------------
__global__ void k_patches(const float* __restrict__ images) {
    int p = blockIdx.x, b = blockIdx.y;
    __nv_bfloat16* dst = g_patb + ((size_t)b * MPAD + p) * KCLIP;
    if (p >= HWc) {
        for (int k = threadIdx.x; k < KCLIP; k += 128) dst[k] = __float2bfloat16(0.f);
        return;
    }
    int pr = p / HPc, pc = p % HPc;
    for (int k = threadIdx.x; k < KCLIP; k += 128) {
        float v = 0.f;
        if (k < PKc) {
            int ch = k / 196, rem = k % 196;
            int dy = rem / PATCHc, dx = rem % PATCHc;
            v = images[(((size_t)b * 4 + ch) * IMGc + (pr * PATCHc + dy)) * IMGc
                       + (pc * PATCHc + dx)];
        }
        dst[k] = __float2bfloat16(v);
    }
}

// ---------------- kernel: gather + LayerNorm -> bf16 ----------------
__global__ void k_prep(const float* __restrict__ feats,
                       const float* __restrict__ gamma,
                       const float* __restrict__ beta) {
    int r = blockIdx.x, jj = blockIdx.y, b = blockIdx.z;
    int tid = threadIdx.x;
    __nv_bfloat16* dst = (jj == Jc)
        ? (g_f24b + ((size_t)b * MPAD + r) * Dc)
        : (g_xnb + (((size_t)b * Jc + jj) * MPAD + r) * Dc);
    if (r >= HWc) {
        uint4 z = make_uint4(0, 0, 0, 0);
        ((uint4*)dst)[tid] = z;
        return;
    }
    int t = g_idx[b] + 1 + (r / HPc) * (HPc + 1) + (r % HPc);
    int l = (jj < Jc) ? (24 - 4 * jj) : 24;
    const float* src = feats + (((size_t)b * Nc + t) * Lc + l) * (size_t)Dc;
    float4 a = ((const float4*)src)[tid * 2];
    float4 c = ((const float4*)src)[tid * 2 + 1];
    if (jj == Jc) {
        uint4 u;
        u.x = pkbf(a.x, a.y); u.y = pkbf(a.z, a.w);
        u.z = pkbf(c.x, c.y); u.w = pkbf(c.z, c.w);
        ((uint4*)dst)[tid] = u;
        return;
    }
    float s  = a.x + a.y + a.z + a.w + c.x + c.y + c.z + c.w;
    float s2 = a.x*a.x + a.y*a.y + a.z*a.z + a.w*a.w + c.x*c.x + c.y*c.y + c.z*c.z + c.w*c.w;
    __shared__ float r1[256], r2[256];
    r1[tid] = s; r2[tid] = s2;
    __syncthreads();
    for (int off = 128; off; off >>= 1) {
        if (tid < off) { r1[tid] += r1[tid + off]; r2[tid] += r2[tid + off]; }
        __syncthreads();
    }
    float mu   = r1[0] * (1.f / Dc);
    float var  = r2[0] * (1.f / Dc) - mu * mu;
    float rstd = rsqrtf(var + LN_EPSc);
    const float4* gg = (const float4*)(gamma + (size_t)jj * Dc);
    const float4* bb = (const float4*)(beta  + (size_t)jj * Dc);
    float4 g0 = gg[tid*2], g1 = gg[tid*2+1];
    float4 b0 = bb[tid*2], b1 = bb[tid*2+1];
    float o0 = (a.x - mu) * rstd * g0.x + b0.x;
    float o1 = (a.y - mu) * rstd * g0.y + b0.y;
    float o2 = (a.z - mu) * rstd * g0.z + b0.z;
    float o3 = (a.w - mu) * rstd * g0.w + b0.w;
    float o4 = (c.x - mu) * rstd * g1.x + b1.x;
    float o5 = (c.y - mu) * rstd * g1.y + b1.y;
    float o6 = (c.z - mu) * rstd * g1.z + b1.z;
    float o7 = (c.w - mu) * rstd * g1.w + b1.w;
    uint4 u;
    u.x = pkbf(o0, o1); u.y = pkbf(o2, o3); u.z = pkbf(o4, o5); u.w = pkbf(o6, o7);
    ((uint4*)dst)[tid] = u;
}

// ---------------- weight conversions (split for DAG scheduling) ----------------
__global__ void k_cvt_norm(const float* __restrict__ nw) {
    int n8 = (int)((size_t)Jc * CLIPc * Dc / 8);
    __nv_bfloat16* d = w_norm;
    for (int i = blockIdx.x * blockDim.x + threadIdx.x; i < n8; i += gridDim.x * blockDim.x) {
        float4 a = ((const float4*)nw)[i * 2];
        float4 c = ((const float4*)nw)[i * 2 + 1];
        uint4 u;
        u.x = pkbf(a.x, a.y); u.y = pkbf(a.z, a.w);
        u.z = pkbf(c.x, c.y); u.w = pkbf(c.z, c.w);
        ((uint4*)d)[i] = u;
    }
}
__global__ void k_cvt_io(const float* __restrict__ iw, const float* __restrict__ ow) {
    const float* s = blockIdx.y ? ow : iw;
    __nv_bfloat16* d = blockIdx.y ? w_output : w_input;
    int n8 = blockIdx.y ? (int)((size_t)CLIPc * CLIPc / 8) : (int)((size_t)CLIPc * Dc / 8);
    for (int i = blockIdx.x * blockDim.x + threadIdx.x; i < n8; i += gridDim.x * blockDim.x) {
        float4 a = ((const float4*)s)[i * 2];
        float4 c = ((const float4*)s)[i * 2 + 1];
        uint4 u;
        u.x = pkbf(a.x, a.y); u.y = pkbf(a.z, a.w);
        u.z = pkbf(c.x, c.y); u.w = pkbf(c.z, c.w);
        ((uint4*)d)[i] = u;
    }
}
__global__ void k_cvt_clip(const float* __restrict__ cw) {
    for (int r = blockIdx.x; r < CLIPc; r += gridDim.x) {
        __nv_bfloat16* d = w_clip + (size_t)r * KCLIP;
        for (int c = threadIdx.x; c < KCLIP; c += blockDim.x)
            d[c] = (c < PKc) ? __float2bfloat16(cw[(size_t)r * PKc + c])
                             : __float2bfloat16(0.f);
    }
}

// =====================================================================
// GEMM A: big-tile vis kernel: CTA 128x256, 512 thr, 2-stage cp.async
// =====================================================================
#define STG2_A 8192
#define STG2_SZ 24576

__global__ void __launch_bounds__(512, 1)
k_vgemm(const __nv_bfloat16* __restrict__ A, const __nv_bfloat16* __restrict__ Bw,
        __nv_bfloat16* __restrict__ C, int K,
        long long aStr, long long bStr, int bMod, long long cStr) {
    __shared__ __align__(128) unsigned char smem[2 * STG2_SZ];
    const int tid = threadIdx.x;
    const int lane = tid & 31, wid = tid >> 5;
    const int wm = wid & 3, wn = wid >> 2;
    const int z = blockIdx.z;
    const int m0 = blockIdx.x * 128, n0 = blockIdx.y * 256;
    const __nv_bfloat16* Ab = A + (long long)z * aStr + (long long)m0 * K;
    const __nv_bfloat16* Bb = Bw + (long long)(z % bMod) * bStr + (long long)n0 * K;
    const uint32_t sb = smem_u32(smem);

    float acc[2][8][4];
    #pragma unroll
    for (int i = 0; i < 2; ++i)
        #pragma unroll
        for (int j = 0; j < 8; ++j)
            #pragma unroll
            for (int h = 0; h < 4; ++h) acc[i][j][h] = 0.f;

    auto load_chunk = [&](int kc, int st) {
        uint32_t base = sb + st * STG2_SZ;
        #pragma unroll
        for (int it = 0; it < 3; ++it) {
            int idx = tid + it * 512;
            int isB = idx >= 512;
            int o = isB ? (idx - 512) : idx;
            int row = o >> 2, s = o & 3;
            int ps = s ^ ((row >> 1) & 3);
            const __nv_bfloat16* g = (isB ? Bb : Ab) + (size_t)row * K + kc * 32 + s * 8;
            cp16(base + (isB ? STG2_A : 0) + (uint32_t)(row * 64 + ps * 16), g);
        }
    };

    load_chunk(0, 0); CP_COMMIT();

    const int NK = K >> 5;
    for (int k = 0; k < NK; ++k) {
        if (k + 1 < NK) load_chunk(k + 1, (k + 1) & 1);
        CP_COMMIT();
        asm volatile("cp.async.wait_group 1;" ::: "memory");
        __syncthreads();

        uint32_t aBase = sb + (k & 1) * STG2_SZ;
        uint32_t bBase = aBase + STG2_A;
        #pragma unroll
        for (int kk = 0; kk < 2; ++kk) {
            uint32_t afr[2][4];
            #pragma unroll
            for (int im = 0; im < 2; ++im) {
                int row = wm * 32 + im * 16 + (lane & 15);
                int s = kk * 2 + (lane >> 4);
                int ps = s ^ ((row >> 1) & 3);
                ldm4(afr[im], aBase + (uint32_t)(row * 64 + ps * 16));
            }
            uint32_t bfr[4][4];
            #pragma unroll
            for (int ip = 0; ip < 4; ++ip) {
                int row = wn * 64 + ip * 16 + (lane & 15);
                int s = kk * 2 + (lane >> 4);
                int ps = s ^ ((row >> 1) & 3);
                ldm4(bfr[ip], bBase + (uint32_t)(row * 64 + ps * 16));
            }
            #pragma unroll
            for (int im = 0; im < 2; ++im)
                #pragma unroll
                for (int in = 0; in < 8; ++in)
                    mma16816(acc[im][in], afr[im],
                             bfr[in >> 1][in & 1], bfr[in >> 1][(in & 1) + 2]);
        }
        __syncthreads();
    }

    __nv_bfloat16* Cb = C + (long long)z * cStr;
    int g = lane >> 2, q = lane & 3;
    #pragma unroll
    for (int im = 0; im < 2; ++im) {
        #pragma unroll
        for (int in = 0; in < 8; ++in) {
            int col = n0 + wn * 64 + in * 8 + q * 2;
            #pragma unroll
            for (int h = 0; h < 2; ++h) {
                int row = m0 + wm * 32 + im * 16 + g + h * 8;
                uint32_t pv = pkbf(acc[im][in][h * 2], acc[im][in][h * 2 + 1]);
                *(uint32_t*)(Cb + (size_t)row * CLIPc + col) = pv;
            }
        }
    }
}

// =====================================================================
// GEMM B: 128x128 fp32-out kernel (clip / inp / out)
// =====================================================================
#define BK 32
#define STAGE_A 8192
#define STAGE_SZ 16384

__global__ void __launch_bounds__(256, 2)
k_mgemm(const __nv_bfloat16* __restrict__ A, const __nv_bfloat16* __restrict__ Bw,
        const float* __restrict__ Cadd, const float* __restrict__ bias,
        float* __restrict__ C, int K,
        long long aStr, long long bStr, int bMod, long long cStr) {
    __shared__ __align__(128) unsigned char smem[3 * STAGE_SZ];
    const int tid = threadIdx.x;
    const int lane = tid & 31, wid = tid >> 5;
    const int wm = wid & 1, wn = wid >> 1;
    const int z = blockIdx.z;
    const int m0 = blockIdx.x * 128, n0 = blockIdx.y * 128;
    const __nv_bfloat16* Ab = A + (long long)z * aStr + (long long)m0 * K;
    const __nv_bfloat16* Bb = Bw + (long long)(z % bMod) * bStr + (long long)n0 * K;
    const uint32_t sb = smem_u32(smem);

    float acc[4][4][4];
    #pragma unroll
    for (int i = 0; i < 4; ++i)
        #pragma unroll
        for (int j = 0; j < 4; ++j)
            #pragma unroll
            for (int h = 0; h < 4; ++h) acc[i][j][h] = 0.f;

    auto load_chunk = [&](int kc, int st) {
        uint32_t base = sb + st * STAGE_SZ;
        #pragma unroll
        for (int it = 0; it < 4; ++it) {
            int idx = tid + it * 256;
            int half = idx >> 9;
            int o = idx & 511;
            int row = o >> 2, s = o & 3;
            int ps = s ^ ((row >> 1) & 3);
            const __nv_bfloat16* g = (half ? Bb : Ab) + (size_t)row * K + kc * BK + s * 8;
            cp16(base + half * STAGE_A + (uint32_t)(row * 64 + ps * 16), g);
        }
    };

    load_chunk(0, 0); CP_COMMIT();
    load_chunk(1, 1); CP_COMMIT();

    const int NK = K >> 5;
    for (int k = 0; k < NK; ++k) {
        asm volatile("cp.async.wait_group 1;" ::: "memory");
        __syncthreads();
        if (k + 2 < NK) load_chunk(k + 2, (k + 2) % 3);
        CP_COMMIT();

        uint32_t aBase = sb + (k % 3) * STAGE_SZ;
        uint32_t bBase = aBase + STAGE_A;
        #pragma unroll
        for (int kk = 0; kk < 2; ++kk) {
            uint32_t afr[4][4];
            #pragma unroll
            for (int im = 0; im < 4; ++im) {
                int row = wm * 64 + im * 16 + (lane & 15);
                int s = kk * 2 + (lane >> 4);
                int ps = s ^ ((row >> 1) & 3);
                ldm4(afr[im], aBase + (uint32_t)(row * 64 + ps * 16));
            }
            uint32_t bfr[2][4];
            #pragma unroll
            for (int ip = 0; ip < 2; ++ip) {
                int row = wn * 32 + ip * 16 + (lane & 15);
                int s = kk * 2 + (lane >> 4);
                int ps = s ^ ((row >> 1) & 3);
                ldm4(bfr[ip], bBase + (uint32_t)(row * 64 + ps * 16));
            }
            #pragma unroll
            for (int im = 0; im < 4; ++im)
                #pragma unroll
                for (int in = 0; in < 4; ++in)
                    mma16816(acc[im][in], afr[im],
                             bfr[in >> 1][in & 1], bfr[in >> 1][(in & 1) + 2]);
        }
        __syncthreads();
    }

    float* Cb = C + (long long)z * cStr;
    const float* CaB = Cadd ? (Cadd + (long long)z * cStr) : nullptr;
    int g = lane >> 2, q = lane & 3;
    #pragma unroll
    for (int im = 0; im < 4; ++im) {
        #pragma unroll
        for (int in = 0; in < 4; ++in) {
            int col = n0 + wn * 32 + in * 8 + q * 2;
            #pragma unroll
            for (int h = 0; h < 2; ++h) {
                int row = m0 + wm * 64 + im * 16 + g + h * 8;
                float2 v = make_float2(acc[im][in][h * 2], acc[im][in][h * 2 + 1]);
                if (bias) { v.x += bias[col]; v.y += bias[col + 1]; }
                if (CaB) {
                    float2 ca = *(const float2*)(CaB + (size_t)row * CLIPc + col);
                    v.x += ca.x; v.y += ca.y;
                }
                *(float2*)(Cb + (size_t)row * CLIPc + col) = v;
            }
        }
    }
}

// ---------------- attention: grid(576, B); padded fuse rows stay zero ----------------
__global__ void k_attn() {
    int r = blockIdx.x, b = blockIdx.y;
    int wid = threadIdx.x >> 5, lane = threadIdx.x & 31;
    const __nv_bfloat16* visb = g_visb + (size_t)b * Jc * MPAD * CLIPc;
    size_t rowoff = (size_t)r * CLIPc + wid * 128 + lane;

    float q[4], kv[6][4];
    #pragma unroll
    for (int t = 0; t < 4; ++t) q[t] = __bfloat162float(visb[rowoff + t * 32]) * SCALEc;
    #pragma unroll
    for (int j = 0; j < 6; ++j)
        #pragma unroll
        for (int t = 0; t < 4; ++t)
            kv[j][t] = __bfloat162float(visb[(size_t)(j + 1) * MPAD * CLIPc + rowoff + t * 32]);

    float lg[6];
    #pragma unroll
    for (int j = 0; j < 6; ++j) {
        float s = 0.f;
        #pragma unroll
        for (int t = 0; t < 4; ++t) s += q[t] * kv[j][t];
        #pragma unroll
        for (int off = 16; off; off >>= 1) s += __shfl_xor_sync(0xFFFFFFFFu, s, off);
        lg[j] = s;
    }
    float m = lg[0];
    #pragma unroll
    for (int j = 1; j < 6; ++j) m = fmaxf(m, lg[j]);
    float w[6], sum = 0.f;
    #pragma unroll
    for (int j = 0; j < 6; ++j) { w[j] = __expf(lg[j] - m); sum += w[j]; }
    float inv = 1.f / sum;
    #pragma unroll
    for (int j = 0; j < 6; ++j) w[j] *= inv;

    __nv_bfloat16* dst = g_fuseb + ((size_t)b * MPAD + r) * CLIPc + wid * 128 + lane;
    #pragma unroll
    for (int t = 0; t < 4; ++t) {
        float f = 0.f;
        #pragma unroll
        for (int j = 0; j < 6; ++j) f += w[j] * kv[j][t];
        dst[t * 32] = __float2bfloat16(f);
    }
}

// ---------------- cosine per row ----------------
__global__ void k_cos() {
    int r = blockIdx.x, b = blockIdx.y;
    int tid = threadIdx.x;
    const float* o = g_outm  + ((size_t)b * MPAD + r) * CLIPc;
    const float* c = g_clipf + ((size_t)b * MPAD + r) * CLIPc;
    float d = 0.f, n1 = 0.f, n2 = 0.f;
    #pragma unroll
    for (int i = 0; i < 4; ++i) {
        int k = tid + i * 256;
        float ov = o[k], cv = c[k];
        d += ov * cv; n1 += ov * ov; n2 += cv * cv;
    }
    __shared__ float rd[256], ra[256], rb[256];
    rd[tid] = d; ra[tid] = n1; rb[tid] = n2;
    __syncthreads();
    for (int off = 128; off; off >>= 1) {
        if (tid < off) { rd[tid] += rd[tid + off]; ra[tid] += ra[tid + off]; rb[tid] += rb[tid + off]; }
        __syncthreads();
    }
    if (tid == 0) {
        float denom = fmaxf(sqrtf(ra[0]) * sqrtf(rb[0]), COS_EPSc);
        g_cos[b * HWc + r] = rd[0] / denom;
    }
}

// ---------------- final deterministic reduction ----------------
__global__ void k_final(float* __restrict__ out) {
    int tid = threadIdx.x;
    float s = 0.f;
    for (int i = tid; i < Bc * HWc; i += 256) s += g_cos[i];
    __shared__ float red[256];
    red[tid] = s;
    __syncthreads();
    for (int off = 128; off; off >>= 1) {
        if (tid < off) red[tid] += red[tid + off];
        __syncthreads();
    }
    if (tid == 0) out[0] = 1.f - red[0] * (1.f / (Bc * HWc));
}

// ---------------- host launch: multi-stream DAG ----------------
extern "C" void kernel_launch(void* const* d_in, const int* in_sizes, int n_in,
                              void* d_out, int out_size) {
    const int*   input_ids  = (const int*)  d_in[0];
    const float* images     = (const float*)d_in[1];
    const float* feats      = (const float*)d_in[2];
    const float* norm_gamma = (const float*)d_in[4];
    const float* norm_beta  = (const float*)d_in[5];
    const float* norm_w     = (const float*)d_in[6];
    const float* input_w    = (const float*)d_in[7];
    const float* input_b    = (const float*)d_in[8];
    const float* output_w   = (const float*)d_in[9];
    const float* output_b   = (const float*)d_in[10];
    const float* clip_w     = (const float*)d_in[11];
    const float* clip_b     = (const float*)d_in[12];

    void* p;
    __nv_bfloat16 *p_patb, *p_xnb, *p_f24b, *p_fuseb, *p_wnorm, *p_winp, *p_wout, *p_wclip, *p_visb;
    float *p_inp, *p_outm, *p_clipf;
    cudaGetSymbolAddress(&p, g_patb);   p_patb  = (__nv_bfloat16*)p;
    cudaGetSymbolAddress(&p, g_xnb);    p_xnb   = (__nv_bfloat16*)p;
    cudaGetSymbolAddress(&p, g_f24b);   p_f24b  = (__nv_bfloat16*)p;
    cudaGetSymbolAddress(&p, g_fuseb);  p_fuseb = (__nv_bfloat16*)p;
    cudaGetSymbolAddress(&p, w_norm);   p_wnorm = (__nv_bfloat16*)p;
    cudaGetSymbolAddress(&p, w_input);  p_winp  = (__nv_bfloat16*)p;
    cudaGetSymbolAddress(&p, w_output); p_wout  = (__nv_bfloat16*)p;
    cudaGetSymbolAddress(&p, w_clip);   p_wclip = (__nv_bfloat16*)p;
    cudaGetSymbolAddress(&p, g_visb);   p_visb  = (__nv_bfloat16*)p;
    cudaGetSymbolAddress(&p, g_inp);    p_inp   = (float*)p;
    cudaGetSymbolAddress(&p, g_outm);   p_outm  = (float*)p;
    cudaGetSymbolAddress(&p, g_clipf);  p_clipf = (float*)p;

    static cudaStream_t s1 = nullptr, s2 = nullptr;
    static cudaEvent_t eRoot, ePrep, eNorm, eInp, eClip;
    if (!s1) {
        cudaStreamCreateWithFlags(&s1, cudaStreamNonBlocking);
        cudaStreamCreateWithFlags(&s2, cudaStreamNonBlocking);
        cudaEventCreateWithFlags(&eRoot, cudaEventDisableTiming);
        cudaEventCreateWithFlags(&ePrep, cudaEventDisableTiming);
        cudaEventCreateWithFlags(&eNorm, cudaEventDisableTiming);
        cudaEventCreateWithFlags(&eInp,  cudaEventDisableTiming);
        cudaEventCreateWithFlags(&eClip, cudaEventDisableTiming);
    }

    // fork side streams off the captured (default) stream
    cudaEventRecord(eRoot, 0);
    cudaStreamWaitEvent(s1, eRoot, 0);
    cudaStreamWaitEvent(s2, eRoot, 0);

    // ---- s0: critical path ----
    k_find_idx<<<1, 256>>>(input_ids);
    k_prep<<<dim3(MPAD, 8, Bc), 256>>>(feats, norm_gamma, norm_beta);
    cudaEventRecord(ePrep, 0);

    // ---- s1: norm weights -> io weights -> inp GEMM ----
    k_cvt_norm<<<2048, 256, 0, s1>>>(norm_w);
    cudaEventRecord(eNorm, s1);
    k_cvt_io<<<dim3(1024, 2), 256, 0, s1>>>(input_w, output_w);
    cudaStreamWaitEvent(s1, ePrep, 0);
    k_mgemm<<<dim3(MPAD / 128, CLIPc / 128, Bc), 256, 0, s1>>>(
        p_f24b, p_winp, nullptr, input_b, p_inp, Dc,
        (long long)MPAD * Dc, 0LL, 1, (long long)MPAD * CLIPc);
    cudaEventRecord(eInp, s1);

    // ---- s2: patches -> clip weights -> clip GEMM ----
    k_patches<<<dim3(MPAD, Bc), 128, 0, s2>>>(images);
    k_cvt_clip<<<1024, 256, 0, s2>>>(clip_w);
    k_mgemm<<<dim3(MPAD / 128, CLIPc / 128, Bc), 256, 0, s2>>>(
        p_patb, p_wclip, nullptr, clip_b, p_clipf, KCLIP,
        (long long)MPAD * KCLIP, 0LL, 1, (long long)MPAD * CLIPc);
    cudaEventRecord(eClip, s2);

    // ---- s0 continues: vis -> attn -> out -> cos -> final ----
    cudaStreamWaitEvent(0, eNorm, 0);
    k_vgemm<<<dim3(MPAD / 128, CLIPc / 256, Bc * Jc), 512>>>(
        p_xnb, p_wnorm, p_visb, Dc,
        (long long)MPAD * Dc, (long long)CLIPc * Dc, Jc, (long long)MPAD * CLIPc);
    k_attn<<<dim3(HWc, Bc), 256>>>();
    cudaStreamWaitEvent(0, eInp, 0);
    k_mgemm<<<dim3(MPAD / 128, CLIPc / 128, Bc), 256>>>(
        p_fuseb, p_wout, p_inp, output_b, p_outm, CLIPc,
        (long long)MPAD * CLIPc, 0LL, 1, (long long)MPAD * CLIPc);
    cudaStreamWaitEvent(0, eClip, 0);
    k_cos<<<dim3(HWc, Bc), 256>>>();
    k_final<<<1, 256>>>((float*)d_out);
}